// round 15
// baseline (speedup 1.0000x reference)
#include <cuda_runtime.h>
#include <cuda_bf16.h>
#include <cstdint>

#define BATCH 1024
#define NG    978
#define NGP   1024         // K padded to 1024 (BK=64-exact; pad stays zero)
#define NNODE (BATCH*NG)   // 1001472
#define NEDGE 20480000
#define H1    2048
#define H2    100
#define H2P   128          // fc2 N padded
#define MROWS 2048         // both encoders stacked: 2*BATCH
#define SPLITK2 8
#define PREPB ((NG*H1 + H1*H2) / 256)   // 8626 prep blocks fused into k_edges

// -------- device scratch (BSS => zero-initialized; pad regions never written) --------
__device__ float2        g_xin[NNODE];            // interleaved {x1, x2}
__device__ float2        g_agg[NNODE];            // interleaved {agg1, agg2}
__device__ __nv_bfloat16 g_H [MROWS*NGP];         // relu(gcn), K-pad 978..1023 = 0
__device__ __nv_bfloat16 g_W1[NGP*H1];            // fc1 weight bf16, K-pad rows stay 0
__device__ __nv_bfloat16 g_A2[MROWS*H1];          // relu(fc1 + b1) bf16
__device__ __nv_bfloat16 g_W2[H1*H2P];            // fc2 weight bf16, cols 100..127 stay 0
__device__ float         g_Op[SPLITK2][MROWS*H2P];// fc2 split-K partials

// -------- PTX helpers --------
__device__ __forceinline__ void cp16s(uint32_t saddr, const void* g) {
    asm volatile("cp.async.cg.shared.global [%0], [%1], 16;" :: "r"(saddr), "l"(g));
}
#define CP_COMMIT()  asm volatile("cp.async.commit_group;")
#define CP_WAIT(N)   asm volatile("cp.async.wait_group %0;" :: "n"(N))

__device__ __forceinline__ void ldsm4(uint32_t* r, uint32_t addr) {
    asm volatile("ldmatrix.sync.aligned.m8n8.x4.shared.b16 {%0,%1,%2,%3}, [%4];"
                 : "=r"(r[0]), "=r"(r[1]), "=r"(r[2]), "=r"(r[3]) : "r"(addr));
}
__device__ __forceinline__ void ldsm4t(uint32_t* r, uint32_t addr) {
    asm volatile("ldmatrix.sync.aligned.m8n8.x4.trans.shared.b16 {%0,%1,%2,%3}, [%4];"
                 : "=r"(r[0]), "=r"(r[1]), "=r"(r[2]), "=r"(r[3]) : "r"(addr));
}
__device__ __forceinline__ void mma16816(float* c, const uint32_t* a, uint32_t b0, uint32_t b1) {
    asm volatile("mma.sync.aligned.m16n8k16.row.col.f32.bf16.bf16.f32 "
                 "{%0,%1,%2,%3}, {%4,%5,%6,%7}, {%8,%9}, {%0,%1,%2,%3};"
                 : "+f"(c[0]), "+f"(c[1]), "+f"(c[2]), "+f"(c[3])
                 : "r"(a[0]), "r"(a[1]), "r"(a[2]), "r"(a[3]), "r"(b0), "r"(b1));
}

// -------- K0: pack inputs, 4 nodes/thread --------
__global__ void __launch_bounds__(256) k_pack(const float* __restrict__ x1,
                                              const float* __restrict__ x2) {
    int i = blockIdx.x * 256 + threadIdx.x;           // < NNODE/4 exactly
    float4 a = reinterpret_cast<const float4*>(x1)[i];
    float4 b = reinterpret_cast<const float4*>(x2)[i];
    float4* xo = reinterpret_cast<float4*>(g_xin);
    float4* ao = reinterpret_cast<float4*>(g_agg);
    xo[2 * i]     = make_float4(a.x, b.x, a.y, b.y);
    xo[2 * i + 1] = make_float4(a.z, b.z, a.w, b.w);
    ao[2 * i]     = make_float4(0.f, 0.f, 0.f, 0.f);
    ao[2 * i + 1] = make_float4(0.f, 0.f, 0.f, 0.f);
}

// -------- K1: fused edges + weight prep, 8 edges/thread --------
// Edges sit at ~84% of the LTS sector-bandwidth cap (L2=92%); 8/thr is the
// measured optimum (16/thr overflows the per-warp LDG queue and regresses).
// Gathers use default-cached loads: the kernel has no competing L1 traffic,
// so any L1 capture of the 8MB g_xin set is free.
__device__ __forceinline__ void redv2(int d, float2 v) {
    asm volatile("red.global.add.v2.f32 [%0], {%1,%2};"
                 :: "l"(g_agg + d), "f"(v.x), "f"(v.y) : "memory");
}

__global__ void __launch_bounds__(256) k_edges(const int* __restrict__ edges,
                                               const float* __restrict__ w1,
                                               const float* __restrict__ w2) {
    int b = blockIdx.x;
    if (b < PREPB) {                                  // weight-prep blocks
        int i = b * 256 + threadIdx.x;
        if (i < NG * H1) { g_W1[i] = __float2bfloat16(w1[i]); return; }
        i -= NG * H1;                                 // i < H1*H2 exactly
        int k = i / H2, c = i - k * H2;
        g_W2[k * H2P + c] = __float2bfloat16(w2[i]);
        return;
    }
    long t = (long)(b - PREPB) * 256 + threadIdx.x;   // < NEDGE/8 exactly
    const int4* sp = reinterpret_cast<const int4*>(edges);
    const int4* dp = reinterpret_cast<const int4*>(edges + NEDGE);
    int4 s0 = __ldcs(sp + 2 * t), s1 = __ldcs(sp + 2 * t + 1);
    int4 d0 = __ldcs(dp + 2 * t), d1 = __ldcs(dp + 2 * t + 1);
    float2 v0 = __ldg(&g_xin[s0.x]);
    float2 v1 = __ldg(&g_xin[s0.y]);
    float2 v2 = __ldg(&g_xin[s0.z]);
    float2 v3 = __ldg(&g_xin[s0.w]);
    float2 v4 = __ldg(&g_xin[s1.x]);
    float2 v5 = __ldg(&g_xin[s1.y]);
    float2 v6 = __ldg(&g_xin[s1.z]);
    float2 v7 = __ldg(&g_xin[s1.w]);
    redv2(d0.x, v0); redv2(d0.y, v1); redv2(d0.z, v2); redv2(d0.w, v3);
    redv2(d1.x, v4); redv2(d1.y, v5); redv2(d1.z, v6); redv2(d1.w, v7);
}

// -------- K2: h = relu(w*agg + b), bf16, 2 nodes/thread --------
__global__ void __launch_bounds__(256) k_h(const float* __restrict__ gw,
                                           const float* __restrict__ gb) {
    int i = blockIdx.x * 256 + threadIdx.x;           // < NNODE/2 exactly
    float w = *gw, b = *gb;
    float4 v = reinterpret_cast<const float4*>(g_agg)[i];
    int n0 = 2 * i;
    int bi = n0 / NG;
    int g  = n0 - bi * NG;                            // always even
    __nv_bfloat162 e1 = __floats2bfloat162_rn(fmaxf(w * v.x + b, 0.f), fmaxf(w * v.z + b, 0.f));
    __nv_bfloat162 e2 = __floats2bfloat162_rn(fmaxf(w * v.y + b, 0.f), fmaxf(w * v.w + b, 0.f));
    *reinterpret_cast<__nv_bfloat162*>(&g_H[(size_t)bi * NGP + g]) = e1;
    *reinterpret_cast<__nv_bfloat162*>(&g_H[(size_t)(BATCH + bi) * NGP + g]) = e2;
}

// -------- K3/K4: raw mma.sync GEMM, 64x64 warp tiles, 3-stage cp.async ring ----
// 128 threads = 4 warps (2x2). Converged configuration (R9/R13, 28.7-29.7us):
// occupancy is register-capped at 2 CTAs/SM regardless of grid (R12 split-K
// test), and 64x64 warp tiles are the frag-bandwidth optimum (R6-R8 sweep).
// MODE 0: fc1  A=g_H(2048x1024)  B=g_W1(1024x2048) -> fused bias+relu -> g_A2 bf16
// MODE 1: fc2  A=g_A2(2048x2048) B=g_W2(2048x128)  -> split-K partials g_Op[z] f32
template <int MODE>
__global__ void __launch_bounds__(128) k_gemm(const float* __restrict__ bias) {
    constexpr int BM = 128, BN = 128, BK = 64;
    constexpr int Kdim = (MODE == 0) ? NGP : H1;
    constexpr int lda  = (MODE == 0) ? NGP : H1;
    constexpr int ldb  = (MODE == 0) ? H1  : H2P;
    constexpr int SPLITK = (MODE == 0) ? 1 : SPLITK2;
    constexpr int KCH  = Kdim / SPLITK;
    constexpr int NITER = KCH / BK;                   // 16 or 4
    constexpr int STG = 32768;                        // bytes per stage (A 16K + B 16K)

    const __nv_bfloat16* __restrict__ A = (MODE == 0) ? g_H  : g_A2;
    const __nv_bfloat16* __restrict__ B = (MODE == 0) ? g_W1 : g_W2;

    extern __shared__ char smraw[];
    const uint32_t sb = (uint32_t)__cvta_generic_to_shared(smraw);
    float* bias_s = reinterpret_cast<float*>(smraw + 3 * STG);

    const int tid = threadIdx.x, wid = tid >> 5, lane = tid & 31;
    const int m0 = blockIdx.x * BM;
    const int n0 = blockIdx.y * BN;
    const int kbeg = blockIdx.z * KCH;
    const int wr = wid & 1;       // m half (64)
    const int wc = wid >> 1;      // n half (64)
    const int lrow = lane & 15;
    const int lcb  = (lane >> 4) << 4;                // 0 or 16 bytes

    if (MODE == 0) bias_s[tid] = bias[n0 + tid];

    float acc[4][8][4];
#pragma unroll
    for (int i = 0; i < 4; i++)
#pragma unroll
        for (int j = 0; j < 8; j++)
#pragma unroll
            for (int e = 0; e < 4; e++) acc[i][j][e] = 0.f;

    // per-stage smem: A[128][128B] at 0, B[64][256B] at 16384; XOR-16B swizzle
    auto fill = [&](int c) {
        uint32_t base = sb + (c % 3) * STG;
        const __nv_bfloat16* Ag = A + (size_t)m0 * lda + kbeg + c * BK;
        const __nv_bfloat16* Bg = B + (size_t)(kbeg + c * BK) * ldb + n0;
#pragma unroll
        for (int q = 0; q < 8; q++) {                 // A: 1024 16B-chunks
            int ch = tid + q * 128;
            int row = ch >> 3, c16 = ch & 7;
            uint32_t off = (uint32_t)(row * 128 + c16 * 16) ^ ((row & 7) << 4);
            cp16s(base + off, Ag + (size_t)row * lda + c16 * 8);
        }
#pragma unroll
        for (int q = 0; q < 8; q++) {                 // B: 1024 16B-chunks
            int ch = tid + q * 128;
            int row = ch >> 4, c16 = ch & 15;
            uint32_t off = (uint32_t)(row * 256 + c16 * 16) ^ ((row & 7) << 4);
            cp16s(base + 16384 + off, Bg + (size_t)row * ldb + c16 * 8);
        }
        CP_COMMIT();
    };

    fill(0);
    fill(1);

    const int arow0 = wr * 64 + lrow;                 // + mi*16
    const int bcol  = (wc * 64) * 2 + lcb;            // + nt*32 bytes

    uint32_t af[2][4][4], bf[2][4][4];

    auto load_frags = [&](uint32_t aBase, uint32_t bBase, int kk, int buf) {
#pragma unroll
        for (int mi = 0; mi < 4; mi++) {
            int row = arow0 + mi * 16;
            uint32_t off = (uint32_t)(row * 128 + kk * 2 + lcb) ^ ((row & 7) << 4);
            ldsm4(af[buf][mi], aBase + off);
        }
#pragma unroll
        for (int nt = 0; nt < 4; nt++) {
            int krow = kk + lrow;
            uint32_t off = (uint32_t)(krow * 256 + bcol + nt * 32) ^ ((krow & 7) << 4);
            ldsm4t(bf[buf][nt], bBase + off);
        }
    };

    for (int it = 0; it < NITER; it++) {
        if (it + 1 < NITER) { CP_WAIT(1); } else { CP_WAIT(0); }
        __syncthreads();                              // single barrier per iter
        uint32_t aBase = sb + (it % 3) * STG;
        uint32_t bBase = aBase + 16384;
        load_frags(aBase, bBase, 0, 0);               // start ldsm immediately
        if (it + 2 < NITER) fill(it + 2);             // writes stage (it-1)%3: safe
#pragma unroll
        for (int ks = 0; ks < BK / 16; ks++) {
            int cur = ks & 1;
            if (ks + 1 < BK / 16) load_frags(aBase, bBase, (ks + 1) * 16, cur ^ 1);
#pragma unroll
            for (int mi = 0; mi < 4; mi++)
#pragma unroll
                for (int nt = 0; nt < 4; nt++) {
                    mma16816(acc[mi][nt * 2],     af[cur][mi], bf[cur][nt][0], bf[cur][nt][1]);
                    mma16816(acc[mi][nt * 2 + 1], af[cur][mi], bf[cur][nt][2], bf[cur][nt][3]);
                }
        }
    }

    // epilogue straight from fragment layout: c0,c1 -> (r, col..col+1); c2,c3 -> r+8
    const int r_base = m0 + wr * 64 + (lane >> 2);
    if (MODE == 0) {
#pragma unroll
        for (int mi = 0; mi < 4; mi++) {
            int r = r_base + mi * 16;
#pragma unroll
            for (int ns = 0; ns < 8; ns++) {
                int col = wc * 64 + (ns >> 1) * 16 + (ns & 1) * 8 + (lane & 3) * 2;
                float b0 = bias_s[col], b1 = bias_s[col + 1];
                float* c = acc[mi][ns];
                __nv_bfloat162 lo = __floats2bfloat162_rn(fmaxf(c[0] + b0, 0.f),
                                                          fmaxf(c[1] + b1, 0.f));
                __nv_bfloat162 hi = __floats2bfloat162_rn(fmaxf(c[2] + b0, 0.f),
                                                          fmaxf(c[3] + b1, 0.f));
                *reinterpret_cast<__nv_bfloat162*>(&g_A2[(size_t)r * H1 + n0 + col]) = lo;
                *reinterpret_cast<__nv_bfloat162*>(&g_A2[(size_t)(r + 8) * H1 + n0 + col]) = hi;
            }
        }
    } else {
        float* C = g_Op[blockIdx.z];
#pragma unroll
        for (int mi = 0; mi < 4; mi++) {
            int r = r_base + mi * 16;
#pragma unroll
            for (int ns = 0; ns < 8; ns++) {
                int col = wc * 64 + (ns >> 1) * 16 + (ns & 1) * 8 + (lane & 3) * 2;
                float* c = acc[mi][ns];
                *reinterpret_cast<float2*>(&C[(size_t)r * H2P + col])       = make_float2(c[0], c[1]);
                *reinterpret_cast<float2*>(&C[(size_t)(r + 8) * H2P + col]) = make_float2(c[2], c[3]);
            }
        }
    }
}

#define GSMEM (3 * 32768 + 512)

// -------- K5: r^2 + predictor MLP, one warp per batch row --------
__global__ void __launch_bounds__(256) k_final(const float* __restrict__ others,
                                               const float* __restrict__ fc2b,
                                               const float* __restrict__ m1w,
                                               const float* __restrict__ m1b,
                                               const float* __restrict__ m2w,
                                               const float* __restrict__ m2b,
                                               float* __restrict__ out) {
    int row  = (blockIdx.x * blockDim.x + threadIdx.x) >> 5;  // 0..1023
    int lane = threadIdx.x & 31;
    float a[4], b[4];
    float sa = 0.f, sb = 0.f;
#pragma unroll
    for (int i = 0; i < 4; i++) {
        int c = lane + i * 32;
        float av = 0.f, bv = 0.f;
        if (c < H2) {
            float bias = fc2b[c];
#pragma unroll
            for (int z = 0; z < SPLITK2; z++) {
                av += g_Op[z][row * H2P + c];
                bv += g_Op[z][(BATCH + row) * H2P + c];
            }
            av += bias; bv += bias;
        }
        a[i] = av; b[i] = bv; sa += av; sb += bv;
    }
#pragma unroll
    for (int o = 16; o > 0; o >>= 1) {
        sa += __shfl_xor_sync(~0u, sa, o);
        sb += __shfl_xor_sync(~0u, sb, o);
    }
    float ma = sa * (1.f / H2), mb = sb * (1.f / H2);
    float sab = 0.f, saa = 0.f, sbb = 0.f;
#pragma unroll
    for (int i = 0; i < 4; i++) {
        int c = lane + i * 32;
        if (c < H2) {
            float da = a[i] - ma, db = b[i] - mb;
            sab += da * db; saa += da * da; sbb += db * db;
        }
    }
#pragma unroll
    for (int o = 16; o > 0; o >>= 1) {
        sab += __shfl_xor_sync(~0u, sab, o);
        saa += __shfl_xor_sync(~0u, saa, o);
        sbb += __shfl_xor_sync(~0u, sbb, o);
    }
    if (lane == 0) {
        float corr = sab / (sqrtf(saa) * sqrtf(sbb));
        float z[5];
        z[0] = corr * corr;
#pragma unroll
        for (int i = 0; i < 4; i++) z[i + 1] = others[row * 4 + i];
        float h[4];
#pragma unroll
        for (int j = 0; j < 4; j++) {
            float s = m1b[j];
#pragma unroll
            for (int i = 0; i < 5; i++) s += z[i] * m1w[i * 4 + j];
            h[j] = fmaxf(s, 0.f);
        }
#pragma unroll
        for (int k = 0; k < 2; k++) {
            float s = m2b[k];
#pragma unroll
            for (int j = 0; j < 4; j++) s += h[j] * m2w[j * 2 + k];
            out[row * 2 + k] = s;
        }
    }
}

extern "C" void kernel_launch(void* const* d_in, const int* in_sizes, int n_in,
                              void* d_out, int out_size) {
    const float* in1    = (const float*)d_in[0];
    const float* in2    = (const float*)d_in[1];
    const int*   edges  = (const int*)d_in[2];
    const float* others = (const float*)d_in[3];
    const float* gw     = (const float*)d_in[4];
    const float* gb     = (const float*)d_in[5];
    const float* w1     = (const float*)d_in[6];
    const float* b1     = (const float*)d_in[7];
    const float* w2     = (const float*)d_in[8];
    const float* b2     = (const float*)d_in[9];
    const float* m1w    = (const float*)d_in[10];
    const float* m1b    = (const float*)d_in[11];
    const float* m2w    = (const float*)d_in[12];
    const float* m2b    = (const float*)d_in[13];
    float* out = (float*)d_out;

    static bool attr_done = false;
    if (!attr_done) {
        cudaFuncSetAttribute(k_gemm<0>, cudaFuncAttributeMaxDynamicSharedMemorySize, GSMEM);
        cudaFuncSetAttribute(k_gemm<1>, cudaFuncAttributeMaxDynamicSharedMemorySize, GSMEM);
        attr_done = true;
    }

    k_pack <<<NNODE / 4 / 256, 256>>>(in1, in2);                  // [0]
    k_edges<<<PREPB + NEDGE / 8 / 256, 256>>>(edges, w1, w2);     // [1] edges(8/thr) + prep
    k_h    <<<NNODE / 2 / 256, 256>>>(gw, gb);                    // [2]
    k_gemm<0><<<dim3(16, 16, 1), 128, GSMEM>>>(b1);               // [3] <- profiled
    k_gemm<1><<<dim3(16, 1, SPLITK2), 128, GSMEM>>>(nullptr);     // [4]
    k_final<<<128, 256>>>(others, b2, m1w, m1b, m2w, m2b, out);   // [5]
}

// round 16
// speedup vs baseline: 1.5628x; 1.5628x over previous
#include <cuda_runtime.h>
#include <cuda_bf16.h>
#include <cstdint>

#define BATCH 1024
#define NG    978
#define NGP   1024         // K padded to 1024 (BK=64-exact; pad stays zero)
#define NNODE (BATCH*NG)   // 1001472
#define NEDGE 20480000
#define H1    2048
#define H2    100
#define H2P   128          // fc2 N padded
#define MROWS 2048         // both encoders stacked: 2*BATCH
#define SPLITK2 8
#define PREPB ((NG*H1 + H1*H2) / 256)   // 8626 prep blocks fused into k_edges

// -------- device scratch (BSS => zero-initialized; pad regions never written) --------
__device__ float2        g_xin[NNODE];            // interleaved {x1, x2}
__device__ float2        g_agg[NNODE];            // interleaved {agg1, agg2}
__device__ __nv_bfloat16 g_H [MROWS*NGP];         // relu(gcn), K-pad 978..1023 = 0
__device__ __nv_bfloat16 g_W1[NGP*H1];            // fc1 weight bf16, K-pad rows stay 0
__device__ __nv_bfloat16 g_A2[MROWS*H1];          // relu(fc1 + b1) bf16
__device__ __nv_bfloat16 g_W2[H1*H2P];            // fc2 weight bf16, cols 100..127 stay 0
__device__ float         g_Op[SPLITK2][MROWS*H2P];// fc2 split-K partials

// -------- PTX helpers --------
__device__ __forceinline__ void cp16s(uint32_t saddr, const void* g) {
    asm volatile("cp.async.cg.shared.global [%0], [%1], 16;" :: "r"(saddr), "l"(g));
}
#define CP_COMMIT()  asm volatile("cp.async.commit_group;")
#define CP_WAIT(N)   asm volatile("cp.async.wait_group %0;" :: "n"(N))

__device__ __forceinline__ void ldsm4(uint32_t* r, uint32_t addr) {
    asm volatile("ldmatrix.sync.aligned.m8n8.x4.shared.b16 {%0,%1,%2,%3}, [%4];"
                 : "=r"(r[0]), "=r"(r[1]), "=r"(r[2]), "=r"(r[3]) : "r"(addr));
}
__device__ __forceinline__ void ldsm4t(uint32_t* r, uint32_t addr) {
    asm volatile("ldmatrix.sync.aligned.m8n8.x4.trans.shared.b16 {%0,%1,%2,%3}, [%4];"
                 : "=r"(r[0]), "=r"(r[1]), "=r"(r[2]), "=r"(r[3]) : "r"(addr));
}
__device__ __forceinline__ void mma16816(float* c, const uint32_t* a, uint32_t b0, uint32_t b1) {
    asm volatile("mma.sync.aligned.m16n8k16.row.col.f32.bf16.bf16.f32 "
                 "{%0,%1,%2,%3}, {%4,%5,%6,%7}, {%8,%9}, {%0,%1,%2,%3};"
                 : "+f"(c[0]), "+f"(c[1]), "+f"(c[2]), "+f"(c[3])
                 : "r"(a[0]), "r"(a[1]), "r"(a[2]), "r"(a[3]), "r"(b0), "r"(b1));
}

// -------- K0: pack inputs, 4 nodes/thread --------
__global__ void __launch_bounds__(256) k_pack(const float* __restrict__ x1,
                                              const float* __restrict__ x2) {
    int i = blockIdx.x * 256 + threadIdx.x;           // < NNODE/4 exactly
    float4 a = reinterpret_cast<const float4*>(x1)[i];
    float4 b = reinterpret_cast<const float4*>(x2)[i];
    float4* xo = reinterpret_cast<float4*>(g_xin);
    float4* ao = reinterpret_cast<float4*>(g_agg);
    xo[2 * i]     = make_float4(a.x, b.x, a.y, b.y);
    xo[2 * i + 1] = make_float4(a.z, b.z, a.w, b.w);
    ao[2 * i]     = make_float4(0.f, 0.f, 0.f, 0.f);
    ao[2 * i + 1] = make_float4(0.f, 0.f, 0.f, 0.f);
}

// -------- K1: fused edges + weight prep, 8 edges/thread --------
// Edges sit at ~84% of the LTS sector-bandwidth cap (L2=92%); 8/thr is the
// measured optimum (16/thr overflows the per-warp LDG queue and regresses).
__device__ __forceinline__ void redv2(int d, float2 v) {
    asm volatile("red.global.add.v2.f32 [%0], {%1,%2};"
                 :: "l"(g_agg + d), "f"(v.x), "f"(v.y) : "memory");
}

__global__ void __launch_bounds__(256) k_edges(const int* __restrict__ edges,
                                               const float* __restrict__ w1,
                                               const float* __restrict__ w2) {
    int b = blockIdx.x;
    if (b < PREPB) {                                  // weight-prep blocks
        int i = b * 256 + threadIdx.x;
        if (i < NG * H1) { g_W1[i] = __float2bfloat16(w1[i]); return; }
        i -= NG * H1;                                 // i < H1*H2 exactly
        int k = i / H2, c = i - k * H2;
        g_W2[k * H2P + c] = __float2bfloat16(w2[i]);
        return;
    }
    long t = (long)(b - PREPB) * 256 + threadIdx.x;   // < NEDGE/8 exactly
    const int4* sp = reinterpret_cast<const int4*>(edges);
    const int4* dp = reinterpret_cast<const int4*>(edges + NEDGE);
    int4 s0 = __ldcs(sp + 2 * t), s1 = __ldcs(sp + 2 * t + 1);
    int4 d0 = __ldcs(dp + 2 * t), d1 = __ldcs(dp + 2 * t + 1);
    float2 v0 = __ldg(&g_xin[s0.x]);
    float2 v1 = __ldg(&g_xin[s0.y]);
    float2 v2 = __ldg(&g_xin[s0.z]);
    float2 v3 = __ldg(&g_xin[s0.w]);
    float2 v4 = __ldg(&g_xin[s1.x]);
    float2 v5 = __ldg(&g_xin[s1.y]);
    float2 v6 = __ldg(&g_xin[s1.z]);
    float2 v7 = __ldg(&g_xin[s1.w]);
    redv2(d0.x, v0); redv2(d0.y, v1); redv2(d0.z, v2); redv2(d0.w, v3);
    redv2(d1.x, v4); redv2(d1.y, v5); redv2(d1.z, v6); redv2(d1.w, v7);
}

// -------- K2: h = relu(w*agg + b), bf16, 2 nodes/thread --------
__global__ void __launch_bounds__(256) k_h(const float* __restrict__ gw,
                                           const float* __restrict__ gb) {
    int i = blockIdx.x * 256 + threadIdx.x;           // < NNODE/2 exactly
    float w = *gw, b = *gb;
    float4 v = reinterpret_cast<const float4*>(g_agg)[i];
    int n0 = 2 * i;
    int bi = n0 / NG;
    int g  = n0 - bi * NG;                            // always even
    __nv_bfloat162 e1 = __floats2bfloat162_rn(fmaxf(w * v.x + b, 0.f), fmaxf(w * v.z + b, 0.f));
    __nv_bfloat162 e2 = __floats2bfloat162_rn(fmaxf(w * v.y + b, 0.f), fmaxf(w * v.w + b, 0.f));
    *reinterpret_cast<__nv_bfloat162*>(&g_H[(size_t)bi * NGP + g]) = e1;
    *reinterpret_cast<__nv_bfloat162*>(&g_H[(size_t)(BATCH + bi) * NGP + g]) = e2;
}

// -------- K3/K4: raw mma.sync GEMM, 64x64 warp tiles, 3-stage cp.async ring ----
// 128 threads = 4 warps (2x2). Converged configuration (R9/R13, 28.7-29.7us):
// occupancy is register-capped at 2 CTAs/SM regardless of grid (R12 split-K
// test), and 64x64 warp tiles are the frag-bandwidth optimum (R6-R8 sweep).
// MODE 0: fc1  A=g_H(2048x1024)  B=g_W1(1024x2048) -> fused bias+relu -> g_A2 bf16
// MODE 1: fc2  A=g_A2(2048x2048) B=g_W2(2048x128)  -> split-K partials g_Op[z] f32
template <int MODE>
__global__ void __launch_bounds__(128) k_gemm(const float* __restrict__ bias) {
    constexpr int BM = 128, BN = 128, BK = 64;
    constexpr int Kdim = (MODE == 0) ? NGP : H1;
    constexpr int lda  = (MODE == 0) ? NGP : H1;
    constexpr int ldb  = (MODE == 0) ? H1  : H2P;
    constexpr int SPLITK = (MODE == 0) ? 1 : SPLITK2;
    constexpr int KCH  = Kdim / SPLITK;
    constexpr int NITER = KCH / BK;                   // 16 or 4
    constexpr int STG = 32768;                        // bytes per stage (A 16K + B 16K)

    const __nv_bfloat16* __restrict__ A = (MODE == 0) ? g_H  : g_A2;
    const __nv_bfloat16* __restrict__ B = (MODE == 0) ? g_W1 : g_W2;

    extern __shared__ char smraw[];
    const uint32_t sb = (uint32_t)__cvta_generic_to_shared(smraw);
    float* bias_s = reinterpret_cast<float*>(smraw + 3 * STG);

    const int tid = threadIdx.x, wid = tid >> 5, lane = tid & 31;
    const int m0 = blockIdx.x * BM;
    const int n0 = blockIdx.y * BN;
    const int kbeg = blockIdx.z * KCH;
    const int wr = wid & 1;       // m half (64)
    const int wc = wid >> 1;      // n half (64)
    const int lrow = lane & 15;
    const int lcb  = (lane >> 4) << 4;                // 0 or 16 bytes

    if (MODE == 0) bias_s[tid] = bias[n0 + tid];

    float acc[4][8][4];
#pragma unroll
    for (int i = 0; i < 4; i++)
#pragma unroll
        for (int j = 0; j < 8; j++)
#pragma unroll
            for (int e = 0; e < 4; e++) acc[i][j][e] = 0.f;

    // per-stage smem: A[128][128B] at 0, B[64][256B] at 16384; XOR-16B swizzle
    auto fill = [&](int c) {
        uint32_t base = sb + (c % 3) * STG;
        const __nv_bfloat16* Ag = A + (size_t)m0 * lda + kbeg + c * BK;
        const __nv_bfloat16* Bg = B + (size_t)(kbeg + c * BK) * ldb + n0;
#pragma unroll
        for (int q = 0; q < 8; q++) {                 // A: 1024 16B-chunks
            int ch = tid + q * 128;
            int row = ch >> 3, c16 = ch & 7;
            uint32_t off = (uint32_t)(row * 128 + c16 * 16) ^ ((row & 7) << 4);
            cp16s(base + off, Ag + (size_t)row * lda + c16 * 8);
        }
#pragma unroll
        for (int q = 0; q < 8; q++) {                 // B: 1024 16B-chunks
            int ch = tid + q * 128;
            int row = ch >> 4, c16 = ch & 15;
            uint32_t off = (uint32_t)(row * 256 + c16 * 16) ^ ((row & 7) << 4);
            cp16s(base + 16384 + off, Bg + (size_t)row * ldb + c16 * 8);
        }
        CP_COMMIT();
    };

    fill(0);
    fill(1);

    const int arow0 = wr * 64 + lrow;                 // + mi*16
    const int bcol  = (wc * 64) * 2 + lcb;            // + nt*32 bytes

    uint32_t af[2][4][4], bf[2][4][4];

    auto load_frags = [&](uint32_t aBase, uint32_t bBase, int kk, int buf) {
#pragma unroll
        for (int mi = 0; mi < 4; mi++) {
            int row = arow0 + mi * 16;
            uint32_t off = (uint32_t)(row * 128 + kk * 2 + lcb) ^ ((row & 7) << 4);
            ldsm4(af[buf][mi], aBase + off);
        }
#pragma unroll
        for (int nt = 0; nt < 4; nt++) {
            int krow = kk + lrow;
            uint32_t off = (uint32_t)(krow * 256 + bcol + nt * 32) ^ ((krow & 7) << 4);
            ldsm4t(bf[buf][nt], bBase + off);
        }
    };

    for (int it = 0; it < NITER; it++) {
        if (it + 1 < NITER) { CP_WAIT(1); } else { CP_WAIT(0); }
        __syncthreads();                              // single barrier per iter
        uint32_t aBase = sb + (it % 3) * STG;
        uint32_t bBase = aBase + 16384;
        load_frags(aBase, bBase, 0, 0);               // start ldsm immediately
        if (it + 2 < NITER) fill(it + 2);             // writes stage (it-1)%3: safe
#pragma unroll
        for (int ks = 0; ks < BK / 16; ks++) {
            int cur = ks & 1;
            if (ks + 1 < BK / 16) load_frags(aBase, bBase, (ks + 1) * 16, cur ^ 1);
#pragma unroll
            for (int mi = 0; mi < 4; mi++)
#pragma unroll
                for (int nt = 0; nt < 4; nt++) {
                    mma16816(acc[mi][nt * 2],     af[cur][mi], bf[cur][nt][0], bf[cur][nt][1]);
                    mma16816(acc[mi][nt * 2 + 1], af[cur][mi], bf[cur][nt][2], bf[cur][nt][3]);
                }
        }
    }

    // epilogue straight from fragment layout: c0,c1 -> (r, col..col+1); c2,c3 -> r+8
    const int r_base = m0 + wr * 64 + (lane >> 2);
    if (MODE == 0) {
#pragma unroll
        for (int mi = 0; mi < 4; mi++) {
            int r = r_base + mi * 16;
#pragma unroll
            for (int ns = 0; ns < 8; ns++) {
                int col = wc * 64 + (ns >> 1) * 16 + (ns & 1) * 8 + (lane & 3) * 2;
                float b0 = bias_s[col], b1 = bias_s[col + 1];
                float* c = acc[mi][ns];
                __nv_bfloat162 lo = __floats2bfloat162_rn(fmaxf(c[0] + b0, 0.f),
                                                          fmaxf(c[1] + b1, 0.f));
                __nv_bfloat162 hi = __floats2bfloat162_rn(fmaxf(c[2] + b0, 0.f),
                                                          fmaxf(c[3] + b1, 0.f));
                *reinterpret_cast<__nv_bfloat162*>(&g_A2[(size_t)r * H1 + n0 + col]) = lo;
                *reinterpret_cast<__nv_bfloat162*>(&g_A2[(size_t)(r + 8) * H1 + n0 + col]) = hi;
            }
        }
    } else {
        float* C = g_Op[blockIdx.z];
#pragma unroll
        for (int mi = 0; mi < 4; mi++) {
            int r = r_base + mi * 16;
#pragma unroll
            for (int ns = 0; ns < 8; ns++) {
                int col = wc * 64 + (ns >> 1) * 16 + (ns & 1) * 8 + (lane & 3) * 2;
                float* c = acc[mi][ns];
                *reinterpret_cast<float2*>(&C[(size_t)r * H2P + col])       = make_float2(c[0], c[1]);
                *reinterpret_cast<float2*>(&C[(size_t)(r + 8) * H2P + col]) = make_float2(c[2], c[3]);
            }
        }
    }
}

#define GSMEM (3 * 32768 + 512)

// -------- K5: r^2 + predictor MLP, one warp per batch row --------
__global__ void __launch_bounds__(256) k_final(const float* __restrict__ others,
                                               const float* __restrict__ fc2b,
                                               const float* __restrict__ m1w,
                                               const float* __restrict__ m1b,
                                               const float* __restrict__ m2w,
                                               const float* __restrict__ m2b,
                                               float* __restrict__ out) {
    int row  = (blockIdx.x * blockDim.x + threadIdx.x) >> 5;  // 0..1023
    int lane = threadIdx.x & 31;
    float a[4], b[4];
    float sa = 0.f, sb = 0.f;
#pragma unroll
    for (int i = 0; i < 4; i++) {
        int c = lane + i * 32;
        float av = 0.f, bv = 0.f;
        if (c < H2) {
            float bias = fc2b[c];
#pragma unroll
            for (int z = 0; z < SPLITK2; z++) {
                av += g_Op[z][row * H2P + c];
                bv += g_Op[z][(BATCH + row) * H2P + c];
            }
            av += bias; bv += bias;
        }
        a[i] = av; b[i] = bv; sa += av; sb += bv;
    }
#pragma unroll
    for (int o = 16; o > 0; o >>= 1) {
        sa += __shfl_xor_sync(~0u, sa, o);
        sb += __shfl_xor_sync(~0u, sb, o);
    }
    float ma = sa * (1.f / H2), mb = sb * (1.f / H2);
    float sab = 0.f, saa = 0.f, sbb = 0.f;
#pragma unroll
    for (int i = 0; i < 4; i++) {
        int c = lane + i * 32;
        if (c < H2) {
            float da = a[i] - ma, db = b[i] - mb;
            sab += da * db; saa += da * da; sbb += db * db;
        }
    }
#pragma unroll
    for (int o = 16; o > 0; o >>= 1) {
        sab += __shfl_xor_sync(~0u, sab, o);
        saa += __shfl_xor_sync(~0u, saa, o);
        sbb += __shfl_xor_sync(~0u, sbb, o);
    }
    if (lane == 0) {
        float corr = sab / (sqrtf(saa) * sqrtf(sbb));
        float z[5];
        z[0] = corr * corr;
#pragma unroll
        for (int i = 0; i < 4; i++) z[i + 1] = others[row * 4 + i];
        float h[4];
#pragma unroll
        for (int j = 0; j < 4; j++) {
            float s = m1b[j];
#pragma unroll
            for (int i = 0; i < 5; i++) s += z[i] * m1w[i * 4 + j];
            h[j] = fmaxf(s, 0.f);
        }
#pragma unroll
        for (int k = 0; k < 2; k++) {
            float s = m2b[k];
#pragma unroll
            for (int j = 0; j < 4; j++) s += h[j] * m2w[j * 2 + k];
            out[row * 2 + k] = s;
        }
    }
}

extern "C" void kernel_launch(void* const* d_in, const int* in_sizes, int n_in,
                              void* d_out, int out_size) {
    const float* in1    = (const float*)d_in[0];
    const float* in2    = (const float*)d_in[1];
    const int*   edges  = (const int*)d_in[2];
    const float* others = (const float*)d_in[3];
    const float* gw     = (const float*)d_in[4];
    const float* gb     = (const float*)d_in[5];
    const float* w1     = (const float*)d_in[6];
    const float* b1     = (const float*)d_in[7];
    const float* w2     = (const float*)d_in[8];
    const float* b2     = (const float*)d_in[9];
    const float* m1w    = (const float*)d_in[10];
    const float* m1b    = (const float*)d_in[11];
    const float* m2w    = (const float*)d_in[12];
    const float* m2b    = (const float*)d_in[13];
    float* out = (float*)d_out;

    static bool attr_done = false;
    if (!attr_done) {
        cudaFuncSetAttribute(k_gemm<0>, cudaFuncAttributeMaxDynamicSharedMemorySize, GSMEM);
        cudaFuncSetAttribute(k_gemm<1>, cudaFuncAttributeMaxDynamicSharedMemorySize, GSMEM);
        attr_done = true;
    }

    k_pack <<<NNODE / 4 / 256, 256>>>(in1, in2);                  // [0]
    k_edges<<<PREPB + NEDGE / 8 / 256, 256>>>(edges, w1, w2);     // [1] edges(8/thr) + prep
    k_h    <<<NNODE / 2 / 256, 256>>>(gw, gb);                    // [2]
    k_gemm<0><<<dim3(16, 16, 1), 128, GSMEM>>>(b1);               // [3] <- profiled
    k_gemm<1><<<dim3(16, 1, SPLITK2), 128, GSMEM>>>(nullptr);     // [4]
    k_final<<<128, 256>>>(others, b2, m1w, m1b, m2w, m2b, out);   // [5]
}